// round 14
// baseline (speedup 1.0000x reference)
#include <cuda_runtime.h>
#include <cuda_fp16.h>
#include <cstdint>

#define B_  2
#define T_  2048
#define C_  768
#define H_  12
#define D_  64
#define M_  (B_ * T_)      // 4096 rows

// Scratch (allocation-free), all fp16
__device__ __half g_xh[(size_t)M_ * C_];
__device__ __half g_wqkv[(size_t)C_ * 3 * C_];
__device__ __half g_wproj[(size_t)C_ * C_];
__device__ __half g_qkvh[(size_t)M_ * 3 * C_];
__device__ __half g_yh[(size_t)M_ * C_];

extern __shared__ char dynsmem[];

// SW128 swizzle: XOR bits[6:4] with bits[9:7]; 16B-granule safe.
#define SW(o) ((o) ^ ((((unsigned)(o)) >> 3) & 0x70))

// ---------------------------------------------------------------------------
// PTX helpers
// ---------------------------------------------------------------------------
__device__ __forceinline__ uint32_t smem_u32(const void* p) {
    uint32_t a;
    asm("{ .reg .u64 t; cvta.to.shared.u64 t, %1; cvt.u32.u64 %0, t; }"
        : "=r"(a) : "l"(p));
    return a;
}

__device__ __forceinline__ void cpa16(uint32_t dst, const void* src) {
    asm volatile("cp.async.cg.shared.global [%0], [%1], 16;" :: "r"(dst), "l"(src));
}
#define CP_COMMIT() asm volatile("cp.async.commit_group;" ::: "memory")
#define CP_WAIT0()  asm volatile("cp.async.wait_group 0;" ::: "memory")
#define CP_WAIT1()  asm volatile("cp.async.wait_group 1;" ::: "memory")

__device__ __forceinline__ void ldsm4(unsigned* r, uint32_t a) {
    asm volatile("ldmatrix.sync.aligned.m8n8.x4.shared.b16 {%0,%1,%2,%3}, [%4];"
        : "=r"(r[0]), "=r"(r[1]), "=r"(r[2]), "=r"(r[3]) : "r"(a));
}
__device__ __forceinline__ void ldsm4t(unsigned* r, uint32_t a) {
    asm volatile("ldmatrix.sync.aligned.m8n8.x4.trans.shared.b16 {%0,%1,%2,%3}, [%4];"
        : "=r"(r[0]), "=r"(r[1]), "=r"(r[2]), "=r"(r[3]) : "r"(a));
}

__device__ __forceinline__ void mma16(float* c, const unsigned* a, const unsigned* b) {
    asm volatile(
        "mma.sync.aligned.m16n8k16.row.col.f32.f16.f16.f32 "
        "{%0,%1,%2,%3}, {%4,%5,%6,%7}, {%8,%9}, {%0,%1,%2,%3};"
        : "+f"(c[0]), "+f"(c[1]), "+f"(c[2]), "+f"(c[3])
        : "r"(a[0]), "r"(a[1]), "r"(a[2]), "r"(a[3]), "r"(b[0]), "r"(b[1]));
}

// ---------------------------------------------------------------------------
// fp32 -> fp16 conversion: one launch for all three tensors
// ---------------------------------------------------------------------------
__global__ void f2h_all(const float* __restrict__ s0, __half* __restrict__ d0, int n0,
                        const float* __restrict__ s1, __half* __restrict__ d1, int n1,
                        const float* __restrict__ s2, __half* __restrict__ d2, int n2) {
    int i = blockIdx.x * blockDim.x + threadIdx.x;
    const float* s; __half* d; int j;
    if (i < n0)               { s = s0; d = d0; j = i; }
    else if (i < n0 + n1)     { s = s1; d = d1; j = i - n0; }
    else if (i < n0 + n1 + n2){ s = s2; d = d2; j = i - n0 - n1; }
    else return;
    float4 v = reinterpret_cast<const float4*>(s)[j];
    __half2* o = reinterpret_cast<__half2*>(d) + 2 * j;
    o[0] = __floats2half2_rn(v.x, v.y);
    o[1] = __floats2half2_rn(v.z, v.w);
}

// ---------------------------------------------------------------------------
// fp16 GEMM: CTA BMT x 128, BK=64, 128 threads (2x2 warps, warp tile
// (BMT/2) x 64), 2-stage cp.async double buffer. fp32 accumulate.
// BMT=64 -> occ 4 (QKV); BMT=32 -> occ 5 single-wave (proj).
// ---------------------------------------------------------------------------
#define SAH 72                         // A smem row stride (halves)
#define SBH 136                        // B smem row stride (halves)

template<int OUT_HALF, int BMT, int MINB>
__global__ void __launch_bounds__(128, MINB)
gemm_h(const __half* __restrict__ A, const __half* __restrict__ W,
       const float* __restrict__ bias, void* __restrict__ outv, int K, int N) {
    constexpr int MT  = BMT / 32;                 // m16 tiles per warp (2 or 1)
    constexpr int ASZ = BMT * SAH * 2;
    constexpr int STG = ASZ + 64 * SBH * 2;
    constexpr int AIT = BMT / 16;                 // A fill iters

    const int tid = threadIdx.x, lane = tid & 31, warp = tid >> 5;
    const int wm = warp >> 1, wn = warp & 1;
    const int g = lane >> 2, t = lane & 3;
    const int rowBase = blockIdx.y * BMT, colBase = blockIdx.x * 128;
    const uint32_t sb = smem_u32(dynsmem);

    auto fill = [&](int s, int k0) {
        uint32_t st = sb + s * STG;
        #pragma unroll
        for (int it = 0; it < AIT; it++) {               // A: BMT rows x 64 halves
            int e = tid + 128 * it, r = e >> 3, c = e & 7;
            cpa16(st + (r * SAH + c * 8) * 2, A + (size_t)(rowBase + r) * K + k0 + c * 8);
        }
        #pragma unroll
        for (int it = 0; it < 8; it++) {                 // B: 64 rows x 128 halves
            int e = tid + 128 * it, r = e >> 4, c = e & 15;
            cpa16(st + ASZ + (r * SBH + c * 8) * 2, W + (size_t)(k0 + r) * N + colBase + c * 8);
        }
    };

    float acc[MT][8][4] = {};

    const int nCh = K / 64;   // 12
    fill(0, 0);  CP_COMMIT();
    fill(1, 64); CP_COMMIT();

    for (int c = 0; c < nCh; c++) {
        if (c + 1 < nCh) CP_WAIT1(); else CP_WAIT0();
        __syncthreads();

        uint32_t st = sb + (c & 1) * STG;
        #pragma unroll
        for (int ks = 0; ks < 4; ks++) {
            unsigned af[MT][4], bf[8][2];
            #pragma unroll
            for (int mt = 0; mt < MT; mt++) {
                int row = wm * (MT * 16) + mt * 16 + (lane & 15);
                ldsm4(af[mt], st + row * (SAH * 2) + ks * 32 + ((lane & 16) ? 16 : 0));
            }
            #pragma unroll
            for (int np = 0; np < 4; np++) {
                int row = ks * 16 + (lane & 15);
                int col = wn * 64 + np * 16 + ((lane & 16) ? 8 : 0);
                unsigned r4[4];
                ldsm4t(r4, st + ASZ + row * (SBH * 2) + col * 2);
                bf[2 * np][0] = r4[0]; bf[2 * np][1] = r4[1];
                bf[2 * np + 1][0] = r4[2]; bf[2 * np + 1][1] = r4[3];
            }
            #pragma unroll
            for (int mt = 0; mt < MT; mt++)
                #pragma unroll
                for (int nt = 0; nt < 8; nt++)
                    mma16(acc[mt][nt], af[mt], bf[nt]);
        }

        if (c + 2 < nCh) {
            __syncthreads();               // all warps done reading stage c&1
            fill(c & 1, (c + 2) * 64);
            CP_COMMIT();
        }
    }

    #pragma unroll
    for (int mt = 0; mt < MT; mt++) {
        int row0 = rowBase + wm * (MT * 16) + mt * 16 + g;
        #pragma unroll
        for (int nt = 0; nt < 8; nt++) {
            int col = colBase + wn * 64 + nt * 8 + 2 * t;
            float b0 = bias[col], b1 = bias[col + 1];
            if (OUT_HALF) {
                __half* out = (__half*)outv;
                *reinterpret_cast<__half2*>(out + (size_t)row0 * N + col) =
                    __floats2half2_rn(acc[mt][nt][0] + b0, acc[mt][nt][1] + b1);
                *reinterpret_cast<__half2*>(out + (size_t)(row0 + 8) * N + col) =
                    __floats2half2_rn(acc[mt][nt][2] + b0, acc[mt][nt][3] + b1);
            } else {
                float* out = (float*)outv;
                *reinterpret_cast<float2*>(out + (size_t)row0 * N + col) =
                    make_float2(acc[mt][nt][0] + b0, acc[mt][nt][1] + b1);
                *reinterpret_cast<float2*>(out + (size_t)(row0 + 8) * N + col) =
                    make_float2(acc[mt][nt][2] + b0, acc[mt][nt][3] + b1);
            }
        }
    }
}

// ---------------------------------------------------------------------------
// fp16 causal flash attention (unchanged from R10/R12): 64-row q-tiles,
// SW128-swizzled smem, occ 4, exp2-domain softmax, 3-stage cp.async.
// ---------------------------------------------------------------------------
#define QSZ   8192                   // 64 x 128B rows
#define KVSZ  8192
#define KVSTG (2 * KVSZ)

__global__ void __launch_bounds__(128, 4)
attn_h(const __half* __restrict__ qkv, __half* __restrict__ y) {
    const int qb = (int)gridDim.x - 1 - (int)blockIdx.x;   // heavy tiles first
    const int bh = blockIdx.y, b = bh / H_, h = bh % H_;
    const int tid = threadIdx.x, lane = tid & 31, warp = tid >> 5;
    const int g = lane >> 2, t = lane & 3, w16 = warp * 16, q0 = qb * 64;
    const size_t rs = 3 * C_;
    const __half* base = qkv + (size_t)b * T_ * rs + h * D_;
    const uint32_t sb = smem_u32(dynsmem);
    const uint32_t sQ = sb, sKV = sb + QSZ;

    auto fillKV = [&](int s, int kb) {
        uint32_t st = sKV + s * KVSTG;
        #pragma unroll
        for (int it = 0; it < 8; it++) {
            int e = tid + 128 * it;          // 1024 segs: 512 K + 512 V
            int hv = e >> 9;
            int r = (e >> 3) & 63, c = e & 7;
            cpa16(st + hv * KVSZ + SW(r * 128 + c * 16),
                  base + (1 + hv) * C_ + (size_t)(kb * 64 + r) * rs + c * 8);
        }
    };

    // Prologue: Q + KV(0) in group 0, KV(1) in group 1.
    #pragma unroll
    for (int it = 0; it < 4; it++) {
        int e = tid + 128 * it, r = e >> 3, c = e & 7;
        cpa16(sQ + SW(r * 128 + c * 16), base + (size_t)(q0 + r) * rs + c * 8);
    }
    const int nkb = qb + 1;
    fillKV(0, 0); CP_COMMIT();
    if (nkb > 1) { fillKV(1, 1); CP_COMMIT(); }

    if (nkb > 1) CP_WAIT1(); else CP_WAIT0();
    __syncthreads();

    // Q fragments, loaded once; fold (1/8)*log2(e) scale into them.
    const __half2 qscale = __float2half2_rn(0.18033688f);   // 0.125 * log2(e)
    unsigned qf[4][4];
    #pragma unroll
    for (int ks = 0; ks < 4; ks++) {
        int row = w16 + (lane & 15);
        ldsm4(qf[ks], sQ + SW(row * 128 + ks * 32 + ((lane & 16) ? 16 : 0)));
        #pragma unroll
        for (int j = 0; j < 4; j++) {
            __half2 v = *reinterpret_cast<__half2*>(&qf[ks][j]);
            v = __hmul2(v, qscale);
            qf[ks][j] = *reinterpret_cast<unsigned*>(&v);
        }
    }

    float oAcc[8][4] = {};
    float m_i[2] = {-1e30f, -1e30f}, l_i[2] = {0.0f, 0.0f};

    for (int kb = 0; kb < nkb; kb++) {
        if (kb + 1 < nkb) CP_WAIT1(); else CP_WAIT0();
        __syncthreads();
        if (kb + 2 < nkb) { fillKV((kb + 2) % 3, kb + 2); CP_COMMIT(); }

        const uint32_t sK = sKV + (kb % 3) * KVSTG;
        const uint32_t sV = sK + KVSZ;

        // ---- S = Q @ K^T  (log2 domain) ----
        float sA[8][4] = {};
        #pragma unroll
        for (int ks = 0; ks < 4; ks++) {
            unsigned bf[8][2];
            #pragma unroll
            for (int np = 0; np < 4; np++) {
                int row = np * 16 + ((lane & 16) ? 8 : 0) + (lane & 7);
                unsigned r4[4];
                ldsm4(r4, sK + SW(row * 128 + ks * 32 + ((lane & 8) ? 16 : 0)));
                bf[2 * np][0] = r4[0]; bf[2 * np][1] = r4[1];
                bf[2 * np + 1][0] = r4[2]; bf[2 * np + 1][1] = r4[3];
            }
            #pragma unroll
            for (int nt = 0; nt < 8; nt++)
                mma16(sA[nt], qf[ks], bf[nt]);
        }

        // causal mask (near-diagonal blocks only)
        if (kb * 64 + 63 > q0 + w16) {
            int qr0 = q0 + w16 + g, qr1 = qr0 + 8;
            #pragma unroll
            for (int nt = 0; nt < 8; nt++) {
                int kc = kb * 64 + nt * 8 + 2 * t;
                if (kc     > qr0) sA[nt][0] = -1e30f;
                if (kc + 1 > qr0) sA[nt][1] = -1e30f;
                if (kc     > qr1) sA[nt][2] = -1e30f;
                if (kc + 1 > qr1) sA[nt][3] = -1e30f;
            }
        }

        // ---- online softmax (exp2 domain; rows g, g+8; quad reduce) ----
        float mx0 = -1e30f, mx1 = -1e30f;
        #pragma unroll
        for (int nt = 0; nt < 8; nt++) {
            mx0 = fmaxf(mx0, fmaxf(sA[nt][0], sA[nt][1]));
            mx1 = fmaxf(mx1, fmaxf(sA[nt][2], sA[nt][3]));
        }
        #pragma unroll
        for (int off = 1; off <= 2; off <<= 1) {
            mx0 = fmaxf(mx0, __shfl_xor_sync(0xffffffffu, mx0, off));
            mx1 = fmaxf(mx1, __shfl_xor_sync(0xffffffffu, mx1, off));
        }
        float mn0 = fmaxf(m_i[0], mx0), mn1 = fmaxf(m_i[1], mx1);
        float al0 = exp2f(m_i[0] - mn0), al1 = exp2f(m_i[1] - mn1);

        unsigned pf[4][4];
        float ps0 = 0.0f, ps1 = 0.0f;
        #pragma unroll
        for (int nt = 0; nt < 8; nt++) {
            float p0 = exp2f(sA[nt][0] - mn0), p1 = exp2f(sA[nt][1] - mn0);
            float p2 = exp2f(sA[nt][2] - mn1), p3 = exp2f(sA[nt][3] - mn1);
            ps0 += p0 + p1; ps1 += p2 + p3;
            __half2 hA = __floats2half2_rn(p0, p1);
            __half2 hB = __floats2half2_rn(p2, p3);
            pf[nt >> 1][(nt & 1) * 2 + 0] = *reinterpret_cast<unsigned*>(&hA);
            pf[nt >> 1][(nt & 1) * 2 + 1] = *reinterpret_cast<unsigned*>(&hB);
        }
        #pragma unroll
        for (int off = 1; off <= 2; off <<= 1) {
            ps0 += __shfl_xor_sync(0xffffffffu, ps0, off);
            ps1 += __shfl_xor_sync(0xffffffffu, ps1, off);
        }
        l_i[0] = l_i[0] * al0 + ps0;
        l_i[1] = l_i[1] * al1 + ps1;
        m_i[0] = mn0; m_i[1] = mn1;
        #pragma unroll
        for (int nt = 0; nt < 8; nt++) {
            oAcc[nt][0] *= al0; oAcc[nt][1] *= al0;
            oAcc[nt][2] *= al1; oAcc[nt][3] *= al1;
        }

        // ---- O += P @ V ----
        #pragma unroll
        for (int kt = 0; kt < 4; kt++) {
            unsigned vf[8][2];
            #pragma unroll
            for (int np = 0; np < 4; np++) {
                int row = kt * 16 + (lane & 15);
                unsigned r4[4];
                ldsm4t(r4, sV + SW(row * 128 + np * 32 + ((lane & 16) ? 16 : 0)));
                vf[2 * np][0] = r4[0]; vf[2 * np][1] = r4[1];
                vf[2 * np + 1][0] = r4[2]; vf[2 * np + 1][1] = r4[3];
            }
            #pragma unroll
            for (int nt = 0; nt < 8; nt++)
                mma16(oAcc[nt], pf[kt], vf[nt]);
        }
    }

    // ---- epilogue: normalize, store y (half) ----
    float inv0 = 1.0f / l_i[0], inv1 = 1.0f / l_i[1];
    int qr = q0 + w16 + g;
    __half* yo = y + ((size_t)b * T_ + qr) * C_ + h * D_;
    #pragma unroll
    for (int nt = 0; nt < 8; nt++) {
        int col = nt * 8 + 2 * t;
        *reinterpret_cast<__half2*>(yo + col) =
            __floats2half2_rn(oAcc[nt][0] * inv0, oAcc[nt][1] * inv0);
        *reinterpret_cast<__half2*>(yo + (size_t)8 * C_ + col) =
            __floats2half2_rn(oAcc[nt][2] * inv1, oAcc[nt][3] * inv1);
    }
}

// ---------------------------------------------------------------------------
extern "C" void kernel_launch(void* const* d_in, const int* in_sizes, int n_in,
                              void* d_out, int out_size) {
    const float* x        = (const float*)d_in[0];
    const float* c_attn_w = (const float*)d_in[1];
    const float* c_attn_b = (const float*)d_in[2];
    const float* c_proj_w = (const float*)d_in[3];
    const float* c_proj_b = (const float*)d_in[4];
    float* out = (float*)d_out;

    __half *xh, *wq, *wp, *qkvh, *yh;
    cudaGetSymbolAddress((void**)&xh,   g_xh);
    cudaGetSymbolAddress((void**)&wq,   g_wqkv);
    cudaGetSymbolAddress((void**)&wp,   g_wproj);
    cudaGetSymbolAddress((void**)&qkvh, g_qkvh);
    cudaGetSymbolAddress((void**)&yh,   g_yh);

    // 0) one-time fp32 -> fp16 conversions (single launch)
    int n0 = (M_ * C_) / 4, n1 = (C_ * 3 * C_) / 4, n2 = (C_ * C_) / 4;
    f2h_all<<<(n0 + n1 + n2 + 255) / 256, 256>>>(x, xh, n0, c_attn_w, wq, n1, c_proj_w, wp, n2);

    // QKV: BMT=64, occ 4. Proj: BMT=32, occ 5, single wave.
    size_t gsQ = (size_t)2 * (64 * SAH * 2 + 64 * SBH * 2);   // 53248 B
    size_t gsP = (size_t)2 * (32 * SAH * 2 + 64 * SBH * 2);   // 44032 B
    cudaFuncSetAttribute((const void*)gemm_h<1, 64, 4>, cudaFuncAttributeMaxDynamicSharedMemorySize, (int)gsQ);
    cudaFuncSetAttribute((const void*)gemm_h<0, 32, 5>, cudaFuncAttributeMaxDynamicSharedMemorySize, (int)gsP);
    size_t as = (size_t)QSZ + 3 * KVSTG;                       // 57344 B -> occ 4
    cudaFuncSetAttribute(attn_h, cudaFuncAttributeMaxDynamicSharedMemorySize, (int)as);

    // 1) QKV projection: tile 64x128, BK=64, occ 4, grid (18,64)
    gemm_h<1, 64, 4><<<dim3((3 * C_) / 128, M_ / 64), 128, gsQ>>>(xh, wq, c_attn_b, qkvh, C_, 3 * C_);

    // 2) Causal flash attention: 64-row q-tiles, grid (32,24)
    attn_h<<<dim3(T_ / 64, B_ * H_), 128, as>>>(qkvh, yh);

    // 3) Output projection: tile 32x128, occ 5, grid (6,128) = single wave
    gemm_h<0, 32, 5><<<dim3(C_ / 128, M_ / 32), 128, gsP>>>(yh, wp, c_proj_b, out, C_, C_);
}

// round 15
// speedup vs baseline: 1.0267x; 1.0267x over previous
#include <cuda_runtime.h>
#include <cuda_fp16.h>
#include <cstdint>

#define B_  2
#define T_  2048
#define C_  768
#define H_  12
#define D_  64
#define M_  (B_ * T_)      // 4096 rows

// Scratch (allocation-free), all fp16
__device__ __half g_xh[(size_t)M_ * C_];
__device__ __half g_wqkv[(size_t)C_ * 3 * C_];
__device__ __half g_wproj[(size_t)C_ * C_];
__device__ __half g_qkvh[(size_t)M_ * 3 * C_];
__device__ __half g_yh[(size_t)M_ * C_];

extern __shared__ char dynsmem[];

// SW128 swizzle: XOR bits[6:4] with bits[9:7]; 16B-granule safe.
#define SW(o) ((o) ^ ((((unsigned)(o)) >> 3) & 0x70))

// ---------------------------------------------------------------------------
// PTX helpers
// ---------------------------------------------------------------------------
__device__ __forceinline__ uint32_t smem_u32(const void* p) {
    uint32_t a;
    asm("{ .reg .u64 t; cvta.to.shared.u64 t, %1; cvt.u32.u64 %0, t; }"
        : "=r"(a) : "l"(p));
    return a;
}

__device__ __forceinline__ void cpa16(uint32_t dst, const void* src) {
    asm volatile("cp.async.cg.shared.global [%0], [%1], 16;" :: "r"(dst), "l"(src));
}
#define CP_COMMIT() asm volatile("cp.async.commit_group;" ::: "memory")
#define CP_WAIT0()  asm volatile("cp.async.wait_group 0;" ::: "memory")
#define CP_WAIT1()  asm volatile("cp.async.wait_group 1;" ::: "memory")

__device__ __forceinline__ void ldsm4(unsigned* r, uint32_t a) {
    asm volatile("ldmatrix.sync.aligned.m8n8.x4.shared.b16 {%0,%1,%2,%3}, [%4];"
        : "=r"(r[0]), "=r"(r[1]), "=r"(r[2]), "=r"(r[3]) : "r"(a));
}
__device__ __forceinline__ void ldsm4t(unsigned* r, uint32_t a) {
    asm volatile("ldmatrix.sync.aligned.m8n8.x4.trans.shared.b16 {%0,%1,%2,%3}, [%4];"
        : "=r"(r[0]), "=r"(r[1]), "=r"(r[2]), "=r"(r[3]) : "r"(a));
}

__device__ __forceinline__ void mma16(float* c, const unsigned* a, const unsigned* b) {
    asm volatile(
        "mma.sync.aligned.m16n8k16.row.col.f32.f16.f16.f32 "
        "{%0,%1,%2,%3}, {%4,%5,%6,%7}, {%8,%9}, {%0,%1,%2,%3};"
        : "+f"(c[0]), "+f"(c[1]), "+f"(c[2]), "+f"(c[3])
        : "r"(a[0]), "r"(a[1]), "r"(a[2]), "r"(a[3]), "r"(b[0]), "r"(b[1]));
}

// ---------------------------------------------------------------------------
// fp32 -> fp16 conversion: one launch for all three tensors
// ---------------------------------------------------------------------------
__global__ void f2h_all(const float* __restrict__ s0, __half* __restrict__ d0, int n0,
                        const float* __restrict__ s1, __half* __restrict__ d1, int n1,
                        const float* __restrict__ s2, __half* __restrict__ d2, int n2) {
    int i = blockIdx.x * blockDim.x + threadIdx.x;
    const float* s; __half* d; int j;
    if (i < n0)               { s = s0; d = d0; j = i; }
    else if (i < n0 + n1)     { s = s1; d = d1; j = i - n0; }
    else if (i < n0 + n1 + n2){ s = s2; d = d2; j = i - n0 - n1; }
    else return;
    float4 v = reinterpret_cast<const float4*>(s)[j];
    __half2* o = reinterpret_cast<__half2*>(d) + 2 * j;
    o[0] = __floats2half2_rn(v.x, v.y);
    o[1] = __floats2half2_rn(v.z, v.w);
}

// ---------------------------------------------------------------------------
// fp16 GEMM: CTA 64 x BNT, BK=64, 128 threads (2x2 warps, warp tile
// 32 x (BNT/2)), 2-stage cp.async double buffer. fp32 accumulate.
// BNT=128 -> occ 4 (QKV); BNT=64 -> occ 5, uniform single-ish waves (proj).
// ---------------------------------------------------------------------------
#define SAH 72                         // A smem row stride (halves)

template<int OUT_HALF, int BNT, int MINB>
__global__ void __launch_bounds__(128, MINB)
gemm_h(const __half* __restrict__ A, const __half* __restrict__ W,
       const float* __restrict__ bias, void* __restrict__ outv, int K, int N) {
    constexpr int NT  = BNT / 16;                 // n8 tiles per warp (8 or 4)
    constexpr int SBH = BNT + 8;                  // B smem row stride (halves)
    constexpr int ASZ = 64 * SAH * 2;             // 9216 B
    constexpr int STG = ASZ + 64 * SBH * 2;
    constexpr int BIT = BNT / 16;                 // B fill iters
    constexpr int BSEG = BNT / 8;                 // B segs per row

    const int tid = threadIdx.x, lane = tid & 31, warp = tid >> 5;
    const int wm = warp >> 1, wn = warp & 1;
    const int g = lane >> 2, t = lane & 3;
    const int rowBase = blockIdx.y * 64, colBase = blockIdx.x * BNT;
    const uint32_t sb = smem_u32(dynsmem);

    auto fill = [&](int s, int k0) {
        uint32_t st = sb + s * STG;
        #pragma unroll
        for (int it = 0; it < 4; it++) {                 // A: 64 rows x 64 halves
            int e = tid + 128 * it, r = e >> 3, c = e & 7;
            cpa16(st + (r * SAH + c * 8) * 2, A + (size_t)(rowBase + r) * K + k0 + c * 8);
        }
        #pragma unroll
        for (int it = 0; it < BIT; it++) {               // B: 64 rows x BNT halves
            int e = tid + 128 * it, r = e / BSEG, c = e % BSEG;
            cpa16(st + ASZ + (r * SBH + c * 8) * 2, W + (size_t)(k0 + r) * N + colBase + c * 8);
        }
    };

    float acc[2][NT][4] = {};

    const int nCh = K / 64;   // 12
    fill(0, 0);  CP_COMMIT();
    fill(1, 64); CP_COMMIT();

    for (int c = 0; c < nCh; c++) {
        if (c + 1 < nCh) CP_WAIT1(); else CP_WAIT0();
        __syncthreads();

        uint32_t st = sb + (c & 1) * STG;
        #pragma unroll
        for (int ks = 0; ks < 4; ks++) {
            unsigned af[2][4], bf[NT][2];
            #pragma unroll
            for (int mt = 0; mt < 2; mt++) {
                int row = wm * 32 + mt * 16 + (lane & 15);
                ldsm4(af[mt], st + row * (SAH * 2) + ks * 32 + ((lane & 16) ? 16 : 0));
            }
            #pragma unroll
            for (int np = 0; np < NT / 2; np++) {
                int row = ks * 16 + (lane & 15);
                int col = wn * (NT * 8) + np * 16 + ((lane & 16) ? 8 : 0);
                unsigned r4[4];
                ldsm4t(r4, st + ASZ + row * (SBH * 2) + col * 2);
                bf[2 * np][0] = r4[0]; bf[2 * np][1] = r4[1];
                bf[2 * np + 1][0] = r4[2]; bf[2 * np + 1][1] = r4[3];
            }
            #pragma unroll
            for (int mt = 0; mt < 2; mt++)
                #pragma unroll
                for (int nt = 0; nt < NT; nt++)
                    mma16(acc[mt][nt], af[mt], bf[nt]);
        }

        if (c + 2 < nCh) {
            __syncthreads();               // all warps done reading stage c&1
            fill(c & 1, (c + 2) * 64);
            CP_COMMIT();
        }
    }

    #pragma unroll
    for (int mt = 0; mt < 2; mt++) {
        int row0 = rowBase + wm * 32 + mt * 16 + g;
        #pragma unroll
        for (int nt = 0; nt < NT; nt++) {
            int col = colBase + wn * (NT * 8) + nt * 8 + 2 * t;
            float b0 = bias[col], b1 = bias[col + 1];
            if (OUT_HALF) {
                __half* out = (__half*)outv;
                *reinterpret_cast<__half2*>(out + (size_t)row0 * N + col) =
                    __floats2half2_rn(acc[mt][nt][0] + b0, acc[mt][nt][1] + b1);
                *reinterpret_cast<__half2*>(out + (size_t)(row0 + 8) * N + col) =
                    __floats2half2_rn(acc[mt][nt][2] + b0, acc[mt][nt][3] + b1);
            } else {
                float* out = (float*)outv;
                *reinterpret_cast<float2*>(out + (size_t)row0 * N + col) =
                    make_float2(acc[mt][nt][0] + b0, acc[mt][nt][1] + b1);
                *reinterpret_cast<float2*>(out + (size_t)(row0 + 8) * N + col) =
                    make_float2(acc[mt][nt][2] + b0, acc[mt][nt][3] + b1);
            }
        }
    }
}

// ---------------------------------------------------------------------------
// fp16 causal flash attention (unchanged from R10/R13): 64-row q-tiles,
// SW128-swizzled smem, occ 4, exp2-domain softmax, 3-stage cp.async.
// ---------------------------------------------------------------------------
#define QSZ   8192                   // 64 x 128B rows
#define KVSZ  8192
#define KVSTG (2 * KVSZ)

__global__ void __launch_bounds__(128, 4)
attn_h(const __half* __restrict__ qkv, __half* __restrict__ y) {
    const int qb = (int)gridDim.x - 1 - (int)blockIdx.x;   // heavy tiles first
    const int bh = blockIdx.y, b = bh / H_, h = bh % H_;
    const int tid = threadIdx.x, lane = tid & 31, warp = tid >> 5;
    const int g = lane >> 2, t = lane & 3, w16 = warp * 16, q0 = qb * 64;
    const size_t rs = 3 * C_;
    const __half* base = qkv + (size_t)b * T_ * rs + h * D_;
    const uint32_t sb = smem_u32(dynsmem);
    const uint32_t sQ = sb, sKV = sb + QSZ;

    auto fillKV = [&](int s, int kb) {
        uint32_t st = sKV + s * KVSTG;
        #pragma unroll
        for (int it = 0; it < 8; it++) {
            int e = tid + 128 * it;          // 1024 segs: 512 K + 512 V
            int hv = e >> 9;
            int r = (e >> 3) & 63, c = e & 7;
            cpa16(st + hv * KVSZ + SW(r * 128 + c * 16),
                  base + (1 + hv) * C_ + (size_t)(kb * 64 + r) * rs + c * 8);
        }
    };

    // Prologue: Q + KV(0) in group 0, KV(1) in group 1.
    #pragma unroll
    for (int it = 0; it < 4; it++) {
        int e = tid + 128 * it, r = e >> 3, c = e & 7;
        cpa16(sQ + SW(r * 128 + c * 16), base + (size_t)(q0 + r) * rs + c * 8);
    }
    const int nkb = qb + 1;
    fillKV(0, 0); CP_COMMIT();
    if (nkb > 1) { fillKV(1, 1); CP_COMMIT(); }

    if (nkb > 1) CP_WAIT1(); else CP_WAIT0();
    __syncthreads();

    // Q fragments, loaded once; fold (1/8)*log2(e) scale into them.
    const __half2 qscale = __float2half2_rn(0.18033688f);   // 0.125 * log2(e)
    unsigned qf[4][4];
    #pragma unroll
    for (int ks = 0; ks < 4; ks++) {
        int row = w16 + (lane & 15);
        ldsm4(qf[ks], sQ + SW(row * 128 + ks * 32 + ((lane & 16) ? 16 : 0)));
        #pragma unroll
        for (int j = 0; j < 4; j++) {
            __half2 v = *reinterpret_cast<__half2*>(&qf[ks][j]);
            v = __hmul2(v, qscale);
            qf[ks][j] = *reinterpret_cast<unsigned*>(&v);
        }
    }

    float oAcc[8][4] = {};
    float m_i[2] = {-1e30f, -1e30f}, l_i[2] = {0.0f, 0.0f};

    for (int kb = 0; kb < nkb; kb++) {
        if (kb + 1 < nkb) CP_WAIT1(); else CP_WAIT0();
        __syncthreads();
        if (kb + 2 < nkb) { fillKV((kb + 2) % 3, kb + 2); CP_COMMIT(); }

        const uint32_t sK = sKV + (kb % 3) * KVSTG;
        const uint32_t sV = sK + KVSZ;

        // ---- S = Q @ K^T  (log2 domain) ----
        float sA[8][4] = {};
        #pragma unroll
        for (int ks = 0; ks < 4; ks++) {
            unsigned bf[8][2];
            #pragma unroll
            for (int np = 0; np < 4; np++) {
                int row = np * 16 + ((lane & 16) ? 8 : 0) + (lane & 7);
                unsigned r4[4];
                ldsm4(r4, sK + SW(row * 128 + ks * 32 + ((lane & 8) ? 16 : 0)));
                bf[2 * np][0] = r4[0]; bf[2 * np][1] = r4[1];
                bf[2 * np + 1][0] = r4[2]; bf[2 * np + 1][1] = r4[3];
            }
            #pragma unroll
            for (int nt = 0; nt < 8; nt++)
                mma16(sA[nt], qf[ks], bf[nt]);
        }

        // causal mask (near-diagonal blocks only)
        if (kb * 64 + 63 > q0 + w16) {
            int qr0 = q0 + w16 + g, qr1 = qr0 + 8;
            #pragma unroll
            for (int nt = 0; nt < 8; nt++) {
                int kc = kb * 64 + nt * 8 + 2 * t;
                if (kc     > qr0) sA[nt][0] = -1e30f;
                if (kc + 1 > qr0) sA[nt][1] = -1e30f;
                if (kc     > qr1) sA[nt][2] = -1e30f;
                if (kc + 1 > qr1) sA[nt][3] = -1e30f;
            }
        }

        // ---- online softmax (exp2 domain; rows g, g+8; quad reduce) ----
        float mx0 = -1e30f, mx1 = -1e30f;
        #pragma unroll
        for (int nt = 0; nt < 8; nt++) {
            mx0 = fmaxf(mx0, fmaxf(sA[nt][0], sA[nt][1]));
            mx1 = fmaxf(mx1, fmaxf(sA[nt][2], sA[nt][3]));
        }
        #pragma unroll
        for (int off = 1; off <= 2; off <<= 1) {
            mx0 = fmaxf(mx0, __shfl_xor_sync(0xffffffffu, mx0, off));
            mx1 = fmaxf(mx1, __shfl_xor_sync(0xffffffffu, mx1, off));
        }
        float mn0 = fmaxf(m_i[0], mx0), mn1 = fmaxf(m_i[1], mx1);
        float al0 = exp2f(m_i[0] - mn0), al1 = exp2f(m_i[1] - mn1);

        unsigned pf[4][4];
        float ps0 = 0.0f, ps1 = 0.0f;
        #pragma unroll
        for (int nt = 0; nt < 8; nt++) {
            float p0 = exp2f(sA[nt][0] - mn0), p1 = exp2f(sA[nt][1] - mn0);
            float p2 = exp2f(sA[nt][2] - mn1), p3 = exp2f(sA[nt][3] - mn1);
            ps0 += p0 + p1; ps1 += p2 + p3;
            __half2 hA = __floats2half2_rn(p0, p1);
            __half2 hB = __floats2half2_rn(p2, p3);
            pf[nt >> 1][(nt & 1) * 2 + 0] = *reinterpret_cast<unsigned*>(&hA);
            pf[nt >> 1][(nt & 1) * 2 + 1] = *reinterpret_cast<unsigned*>(&hB);
        }
        #pragma unroll
        for (int off = 1; off <= 2; off <<= 1) {
            ps0 += __shfl_xor_sync(0xffffffffu, ps0, off);
            ps1 += __shfl_xor_sync(0xffffffffu, ps1, off);
        }
        l_i[0] = l_i[0] * al0 + ps0;
        l_i[1] = l_i[1] * al1 + ps1;
        m_i[0] = mn0; m_i[1] = mn1;
        #pragma unroll
        for (int nt = 0; nt < 8; nt++) {
            oAcc[nt][0] *= al0; oAcc[nt][1] *= al0;
            oAcc[nt][2] *= al1; oAcc[nt][3] *= al1;
        }

        // ---- O += P @ V ----
        #pragma unroll
        for (int kt = 0; kt < 4; kt++) {
            unsigned vf[8][2];
            #pragma unroll
            for (int np = 0; np < 4; np++) {
                int row = kt * 16 + (lane & 15);
                unsigned r4[4];
                ldsm4t(r4, sV + SW(row * 128 + np * 32 + ((lane & 16) ? 16 : 0)));
                vf[2 * np][0] = r4[0]; vf[2 * np][1] = r4[1];
                vf[2 * np + 1][0] = r4[2]; vf[2 * np + 1][1] = r4[3];
            }
            #pragma unroll
            for (int nt = 0; nt < 8; nt++)
                mma16(oAcc[nt], pf[kt], vf[nt]);
        }
    }

    // ---- epilogue: normalize, store y (half) ----
    float inv0 = 1.0f / l_i[0], inv1 = 1.0f / l_i[1];
    int qr = q0 + w16 + g;
    __half* yo = y + ((size_t)b * T_ + qr) * C_ + h * D_;
    #pragma unroll
    for (int nt = 0; nt < 8; nt++) {
        int col = nt * 8 + 2 * t;
        *reinterpret_cast<__half2*>(yo + col) =
            __floats2half2_rn(oAcc[nt][0] * inv0, oAcc[nt][1] * inv0);
        *reinterpret_cast<__half2*>(yo + (size_t)8 * C_ + col) =
            __floats2half2_rn(oAcc[nt][2] * inv1, oAcc[nt][3] * inv1);
    }
}

// ---------------------------------------------------------------------------
extern "C" void kernel_launch(void* const* d_in, const int* in_sizes, int n_in,
                              void* d_out, int out_size) {
    const float* x        = (const float*)d_in[0];
    const float* c_attn_w = (const float*)d_in[1];
    const float* c_attn_b = (const float*)d_in[2];
    const float* c_proj_w = (const float*)d_in[3];
    const float* c_proj_b = (const float*)d_in[4];
    float* out = (float*)d_out;

    __half *xh, *wq, *wp, *qkvh, *yh;
    cudaGetSymbolAddress((void**)&xh,   g_xh);
    cudaGetSymbolAddress((void**)&wq,   g_wqkv);
    cudaGetSymbolAddress((void**)&wp,   g_wproj);
    cudaGetSymbolAddress((void**)&qkvh, g_qkvh);
    cudaGetSymbolAddress((void**)&yh,   g_yh);

    // 0) one-time fp32 -> fp16 conversions (single launch)
    int n0 = (M_ * C_) / 4, n1 = (C_ * 3 * C_) / 4, n2 = (C_ * C_) / 4;
    f2h_all<<<(n0 + n1 + n2 + 255) / 256, 256>>>(x, xh, n0, c_attn_w, wq, n1, c_proj_w, wp, n2);

    // QKV: 64x128 tile, occ 4 (R13 winner). Proj: 64x64 tile, occ 5, ~1 wave.
    size_t gsQ = (size_t)2 * (64 * SAH * 2 + 64 * 136 * 2);   // 53248 B
    size_t gsP = (size_t)2 * (64 * SAH * 2 + 64 * 72 * 2);    // 36864 B
    cudaFuncSetAttribute((const void*)gemm_h<1, 128, 4>, cudaFuncAttributeMaxDynamicSharedMemorySize, (int)gsQ);
    cudaFuncSetAttribute((const void*)gemm_h<0, 64, 5>,  cudaFuncAttributeMaxDynamicSharedMemorySize, (int)gsP);
    size_t as = (size_t)QSZ + 3 * KVSTG;                       // 57344 B -> occ 4
    cudaFuncSetAttribute(attn_h, cudaFuncAttributeMaxDynamicSharedMemorySize, (int)as);

    // 1) QKV projection: tile 64x128, BK=64, occ 4, grid (18,64)
    gemm_h<1, 128, 4><<<dim3((3 * C_) / 128, M_ / 64), 128, gsQ>>>(xh, wq, c_attn_b, qkvh, C_, 3 * C_);

    // 2) Causal flash attention: 64-row q-tiles, grid (32,24)
    attn_h<<<dim3(T_ / 64, B_ * H_), 128, as>>>(qkvh, yh);

    // 3) Output projection: tile 64x64, occ 5, grid (12,64) = ~1.04 waves
    gemm_h<0, 64, 5><<<dim3(C_ / 64, M_ / 64), 128, gsP>>>(yh, wp, c_proj_b, out, C_, C_);
}

// round 16
// speedup vs baseline: 1.0562x; 1.0287x over previous
#include <cuda_runtime.h>
#include <cuda_fp16.h>
#include <cstdint>

#define B_  2
#define T_  2048
#define C_  768
#define H_  12
#define D_  64
#define M_  (B_ * T_)      // 4096 rows

// Scratch (allocation-free), all fp16
__device__ __half g_xh[(size_t)M_ * C_];
__device__ __half g_wqkv[(size_t)C_ * 3 * C_];
__device__ __half g_wproj[(size_t)C_ * C_];
__device__ __half g_qkvh[(size_t)M_ * 3 * C_];
__device__ __half g_yh[(size_t)M_ * C_];

extern __shared__ char dynsmem[];

// SW128 swizzle: XOR bits[6:4] with bits[9:7]; 16B-granule safe (1KB-aligned tiles).
#define SW(o) ((o) ^ ((((unsigned)(o)) >> 3) & 0x70))

// ---------------------------------------------------------------------------
// PTX helpers
// ---------------------------------------------------------------------------
__device__ __forceinline__ uint32_t smem_u32(const void* p) {
    uint32_t a;
    asm("{ .reg .u64 t; cvta.to.shared.u64 t, %1; cvt.u32.u64 %0, t; }"
        : "=r"(a) : "l"(p));
    return a;
}

__device__ __forceinline__ void cpa16(uint32_t dst, const void* src) {
    asm volatile("cp.async.cg.shared.global [%0], [%1], 16;" :: "r"(dst), "l"(src));
}
#define CP_COMMIT() asm volatile("cp.async.commit_group;" ::: "memory")
#define CP_WAIT0()  asm volatile("cp.async.wait_group 0;" ::: "memory")
#define CP_WAIT1()  asm volatile("cp.async.wait_group 1;" ::: "memory")

__device__ __forceinline__ void ldsm4(unsigned* r, uint32_t a) {
    asm volatile("ldmatrix.sync.aligned.m8n8.x4.shared.b16 {%0,%1,%2,%3}, [%4];"
        : "=r"(r[0]), "=r"(r[1]), "=r"(r[2]), "=r"(r[3]) : "r"(a));
}
__device__ __forceinline__ void ldsm4t(unsigned* r, uint32_t a) {
    asm volatile("ldmatrix.sync.aligned.m8n8.x4.trans.shared.b16 {%0,%1,%2,%3}, [%4];"
        : "=r"(r[0]), "=r"(r[1]), "=r"(r[2]), "=r"(r[3]) : "r"(a));
}

__device__ __forceinline__ void mma16(float* c, const unsigned* a, const unsigned* b) {
    asm volatile(
        "mma.sync.aligned.m16n8k16.row.col.f32.f16.f16.f32 "
        "{%0,%1,%2,%3}, {%4,%5,%6,%7}, {%8,%9}, {%0,%1,%2,%3};"
        : "+f"(c[0]), "+f"(c[1]), "+f"(c[2]), "+f"(c[3])
        : "r"(a[0]), "r"(a[1]), "r"(a[2]), "r"(a[3]), "r"(b[0]), "r"(b[1]));
}

// ---------------------------------------------------------------------------
// fp32 -> fp16 conversion: one launch for all three tensors
// ---------------------------------------------------------------------------
__global__ void f2h_all(const float* __restrict__ s0, __half* __restrict__ d0, int n0,
                        const float* __restrict__ s1, __half* __restrict__ d1, int n1,
                        const float* __restrict__ s2, __half* __restrict__ d2, int n2) {
    int i = blockIdx.x * blockDim.x + threadIdx.x;
    const float* s; __half* d; int j;
    if (i < n0)               { s = s0; d = d0; j = i; }
    else if (i < n0 + n1)     { s = s1; d = d1; j = i - n0; }
    else if (i < n0 + n1 + n2){ s = s2; d = d2; j = i - n0 - n1; }
    else return;
    float4 v = reinterpret_cast<const float4*>(s)[j];
    __half2* o = reinterpret_cast<__half2*>(d) + 2 * j;
    o[0] = __floats2half2_rn(v.x, v.y);
    o[1] = __floats2half2_rn(v.z, v.w);
}

// ---------------------------------------------------------------------------
// QKV GEMM (R13 config): CTA 64x128, BK=64, 128 threads, 2-stage, occ 4.
// ---------------------------------------------------------------------------
#define QAH 72
#define QBH 136
#define QASZ (64 * QAH * 2)            // 9216 B
#define QSTG (QASZ + 64 * QBH * 2)     // 26624 B

__global__ void __launch_bounds__(128, 4)
gemm_q(const __half* __restrict__ A, const __half* __restrict__ W,
       const float* __restrict__ bias, __half* __restrict__ out, int K, int N) {
    const int tid = threadIdx.x, lane = tid & 31, warp = tid >> 5;
    const int wm = warp >> 1, wn = warp & 1;
    const int g = lane >> 2, t = lane & 3;
    const int rowBase = blockIdx.y * 64, colBase = blockIdx.x * 128;
    const uint32_t sb = smem_u32(dynsmem);

    auto fill = [&](int s, int k0) {
        uint32_t st = sb + s * QSTG;
        #pragma unroll
        for (int it = 0; it < 4; it++) {
            int e = tid + 128 * it, r = e >> 3, c = e & 7;
            cpa16(st + (r * QAH + c * 8) * 2, A + (size_t)(rowBase + r) * K + k0 + c * 8);
        }
        #pragma unroll
        for (int it = 0; it < 8; it++) {
            int e = tid + 128 * it, r = e >> 4, c = e & 15;
            cpa16(st + QASZ + (r * QBH + c * 8) * 2, W + (size_t)(k0 + r) * N + colBase + c * 8);
        }
    };

    float acc[2][8][4] = {};

    const int nCh = K / 64;   // 12
    fill(0, 0);  CP_COMMIT();
    fill(1, 64); CP_COMMIT();

    for (int c = 0; c < nCh; c++) {
        if (c + 1 < nCh) CP_WAIT1(); else CP_WAIT0();
        __syncthreads();

        uint32_t st = sb + (c & 1) * QSTG;
        #pragma unroll
        for (int ks = 0; ks < 4; ks++) {
            unsigned af[2][4], bf[8][2];
            #pragma unroll
            for (int mt = 0; mt < 2; mt++) {
                int row = wm * 32 + mt * 16 + (lane & 15);
                ldsm4(af[mt], st + row * (QAH * 2) + ks * 32 + ((lane & 16) ? 16 : 0));
            }
            #pragma unroll
            for (int np = 0; np < 4; np++) {
                int row = ks * 16 + (lane & 15);
                int col = wn * 64 + np * 16 + ((lane & 16) ? 8 : 0);
                unsigned r4[4];
                ldsm4t(r4, st + QASZ + row * (QBH * 2) + col * 2);
                bf[2 * np][0] = r4[0]; bf[2 * np][1] = r4[1];
                bf[2 * np + 1][0] = r4[2]; bf[2 * np + 1][1] = r4[3];
            }
            #pragma unroll
            for (int mt = 0; mt < 2; mt++)
                #pragma unroll
                for (int nt = 0; nt < 8; nt++)
                    mma16(acc[mt][nt], af[mt], bf[nt]);
        }

        if (c + 2 < nCh) {
            __syncthreads();
            fill(c & 1, (c + 2) * 64);
            CP_COMMIT();
        }
    }

    #pragma unroll
    for (int mt = 0; mt < 2; mt++) {
        int row0 = rowBase + wm * 32 + mt * 16 + g;
        #pragma unroll
        for (int nt = 0; nt < 8; nt++) {
            int col = colBase + wn * 64 + nt * 8 + 2 * t;
            float b0 = bias[col], b1 = bias[col + 1];
            *reinterpret_cast<__half2*>(out + (size_t)row0 * N + col) =
                __floats2half2_rn(acc[mt][nt][0] + b0, acc[mt][nt][1] + b1);
            *reinterpret_cast<__half2*>(out + (size_t)(row0 + 8) * N + col) =
                __floats2half2_rn(acc[mt][nt][2] + b0, acc[mt][nt][3] + b1);
        }
    }
}

// ---------------------------------------------------------------------------
// Proj GEMM (R12 config, measured 22.3us): CTA 64x128, BK=32, 3-stage, occ 4.
// ---------------------------------------------------------------------------
#define PAH 40
#define PBH 136
#define PASZ (64 * PAH * 2)            // 5120 B
#define PSTG (PASZ + 32 * PBH * 2)     // 13824 B

__global__ void __launch_bounds__(128, 4)
gemm_p(const __half* __restrict__ A, const __half* __restrict__ W,
       const float* __restrict__ bias, float* __restrict__ out, int K, int N) {
    const int tid = threadIdx.x, lane = tid & 31, warp = tid >> 5;
    const int wm = warp >> 1, wn = warp & 1;
    const int g = lane >> 2, t = lane & 3;
    const int rowBase = blockIdx.y * 64, colBase = blockIdx.x * 128;
    const uint32_t sb = smem_u32(dynsmem);

    auto fill = [&](int s, int k0) {
        uint32_t st = sb + s * PSTG;
        #pragma unroll
        for (int it = 0; it < 2; it++) {
            int e = tid + 128 * it, r = e >> 2, c = e & 3;
            cpa16(st + (r * PAH + c * 8) * 2, A + (size_t)(rowBase + r) * K + k0 + c * 8);
        }
        #pragma unroll
        for (int it = 0; it < 4; it++) {
            int e = tid + 128 * it, r = e >> 4, c = e & 15;
            cpa16(st + PASZ + (r * PBH + c * 8) * 2, W + (size_t)(k0 + r) * N + colBase + c * 8);
        }
    };

    float acc[2][8][4] = {};

    const int nCh = K / 32;   // 24
    fill(0, 0);  CP_COMMIT();
    fill(1, 32); CP_COMMIT();

    for (int c = 0; c < nCh; c++) {
        if (c + 1 < nCh) CP_WAIT1(); else CP_WAIT0();
        __syncthreads();
        if (c + 2 < nCh) { fill((c + 2) % 3, (c + 2) * 32); CP_COMMIT(); }

        uint32_t st = sb + (c % 3) * PSTG;
        #pragma unroll
        for (int ks = 0; ks < 2; ks++) {
            unsigned af[2][4], bf[8][2];
            #pragma unroll
            for (int mt = 0; mt < 2; mt++) {
                int row = wm * 32 + mt * 16 + (lane & 15);
                ldsm4(af[mt], st + row * (PAH * 2) + ks * 32 + ((lane & 16) ? 16 : 0));
            }
            #pragma unroll
            for (int np = 0; np < 4; np++) {
                int row = ks * 16 + (lane & 15);
                int col = wn * 64 + np * 16 + ((lane & 16) ? 8 : 0);
                unsigned r4[4];
                ldsm4t(r4, st + PASZ + row * (PBH * 2) + col * 2);
                bf[2 * np][0] = r4[0]; bf[2 * np][1] = r4[1];
                bf[2 * np + 1][0] = r4[2]; bf[2 * np + 1][1] = r4[3];
            }
            #pragma unroll
            for (int mt = 0; mt < 2; mt++)
                #pragma unroll
                for (int nt = 0; nt < 8; nt++)
                    mma16(acc[mt][nt], af[mt], bf[nt]);
        }
    }

    #pragma unroll
    for (int mt = 0; mt < 2; mt++) {
        int row0 = rowBase + wm * 32 + mt * 16 + g;
        #pragma unroll
        for (int nt = 0; nt < 8; nt++) {
            int col = colBase + wn * 64 + nt * 8 + 2 * t;
            float b0 = bias[col], b1 = bias[col + 1];
            *reinterpret_cast<float2*>(out + (size_t)row0 * N + col) =
                make_float2(acc[mt][nt][0] + b0, acc[mt][nt][1] + b1);
            *reinterpret_cast<float2*>(out + (size_t)(row0 + 8) * N + col) =
                make_float2(acc[mt][nt][2] + b0, acc[mt][nt][3] + b1);
        }
    }
}

// ---------------------------------------------------------------------------
// fp16 causal flash attention: 64-row q-tiles, 128-KEY blocks (halved
// per-block overhead), 2-stage cp.async, SW128 smem, occ 3, exp2 softmax.
// ---------------------------------------------------------------------------
#define QSZ    8192                  // 64 q-rows x 128B
#define KVSZ2  16384                 // 128 kv-rows x 128B
#define KVSTG2 (2 * KVSZ2)           // 32 KB per stage

__global__ void __launch_bounds__(128, 3)
attn_h(const __half* __restrict__ qkv, __half* __restrict__ y) {
    const int qb = (int)gridDim.x - 1 - (int)blockIdx.x;   // heavy tiles first
    const int bh = blockIdx.y, b = bh / H_, h = bh % H_;
    const int tid = threadIdx.x, lane = tid & 31, warp = tid >> 5;
    const int g = lane >> 2, t = lane & 3, w16 = warp * 16, q0 = qb * 64;
    const size_t rs = 3 * C_;
    const __half* base = qkv + (size_t)b * T_ * rs + h * D_;
    const uint32_t sb = smem_u32(dynsmem);
    const uint32_t sQ = sb, sKV = sb + QSZ;

    auto fillKV = [&](int s, int kb) {   // kb indexes 128-key blocks
        uint32_t st = sKV + s * KVSTG2;
        #pragma unroll
        for (int it = 0; it < 16; it++) {
            int e = tid + 128 * it;          // 2048 segs: 1024 K + 1024 V
            int hv = e >> 10;
            int r = (e >> 3) & 127, c = e & 7;
            cpa16(st + hv * KVSZ2 + SW(r * 128 + c * 16),
                  base + (1 + hv) * C_ + (size_t)(kb * 128 + r) * rs + c * 8);
        }
    };

    // Prologue: Q + KV(0) in group 0, KV(1) in group 1.
    #pragma unroll
    for (int it = 0; it < 4; it++) {
        int e = tid + 128 * it, r = e >> 3, c = e & 7;
        cpa16(sQ + SW(r * 128 + c * 16), base + (size_t)(q0 + r) * rs + c * 8);
    }
    const int nkb = qb / 2 + 1;
    fillKV(0, 0); CP_COMMIT();
    if (nkb > 1) { fillKV(1, 1); CP_COMMIT(); }

    if (nkb > 1) CP_WAIT1(); else CP_WAIT0();
    __syncthreads();

    // Q fragments, loaded once; fold (1/8)*log2(e) scale into them.
    const __half2 qscale = __float2half2_rn(0.18033688f);   // 0.125 * log2(e)
    unsigned qf[4][4];
    #pragma unroll
    for (int ks = 0; ks < 4; ks++) {
        int row = w16 + (lane & 15);
        ldsm4(qf[ks], sQ + SW(row * 128 + ks * 32 + ((lane & 16) ? 16 : 0)));
        #pragma unroll
        for (int j = 0; j < 4; j++) {
            __half2 v = *reinterpret_cast<__half2*>(&qf[ks][j]);
            v = __hmul2(v, qscale);
            qf[ks][j] = *reinterpret_cast<unsigned*>(&v);
        }
    }

    float oAcc[8][4] = {};
    float m_i[2] = {-1e30f, -1e30f}, l_i[2] = {0.0f, 0.0f};

    for (int kb = 0; kb < nkb; kb++) {
        if (kb > 0) {
            if (kb + 1 < nkb) CP_WAIT1(); else CP_WAIT0();
            __syncthreads();
        }
        const uint32_t sK = sKV + (kb & 1) * KVSTG2;
        const uint32_t sV = sK + KVSZ2;

        // ---- S = Q @ K^T (16 n-tiles, bf loaded in two halves per ks) ----
        float sA[16][4] = {};
        #pragma unroll
        for (int ks = 0; ks < 4; ks++) {
            #pragma unroll
            for (int half = 0; half < 2; half++) {
                unsigned bf[8][2];
                #pragma unroll
                for (int np = 0; np < 4; np++) {
                    int row = (half * 4 + np) * 16 + ((lane & 16) ? 8 : 0) + (lane & 7);
                    unsigned r4[4];
                    ldsm4(r4, sK + SW(row * 128 + ks * 32 + ((lane & 8) ? 16 : 0)));
                    bf[2 * np][0] = r4[0]; bf[2 * np][1] = r4[1];
                    bf[2 * np + 1][0] = r4[2]; bf[2 * np + 1][1] = r4[3];
                }
                #pragma unroll
                for (int j = 0; j < 8; j++)
                    mma16(sA[half * 8 + j], qf[ks], bf[j]);
            }
        }

        // causal mask (near/above-diagonal blocks only)
        if (kb * 128 + 127 > q0 + w16) {
            int qr0 = q0 + w16 + g, qr1 = qr0 + 8;
            #pragma unroll
            for (int nt = 0; nt < 16; nt++) {
                int kc = kb * 128 + nt * 8 + 2 * t;
                if (kc     > qr0) sA[nt][0] = -1e30f;
                if (kc + 1 > qr0) sA[nt][1] = -1e30f;
                if (kc     > qr1) sA[nt][2] = -1e30f;
                if (kc + 1 > qr1) sA[nt][3] = -1e30f;
            }
        }

        // ---- online softmax (exp2 domain; rows g, g+8; quad reduce) ----
        float mx0 = -1e30f, mx1 = -1e30f;
        #pragma unroll
        for (int nt = 0; nt < 16; nt++) {
            mx0 = fmaxf(mx0, fmaxf(sA[nt][0], sA[nt][1]));
            mx1 = fmaxf(mx1, fmaxf(sA[nt][2], sA[nt][3]));
        }
        #pragma unroll
        for (int off = 1; off <= 2; off <<= 1) {
            mx0 = fmaxf(mx0, __shfl_xor_sync(0xffffffffu, mx0, off));
            mx1 = fmaxf(mx1, __shfl_xor_sync(0xffffffffu, mx1, off));
        }
        float mn0 = fmaxf(m_i[0], mx0), mn1 = fmaxf(m_i[1], mx1);
        float al0 = exp2f(m_i[0] - mn0), al1 = exp2f(m_i[1] - mn1);

        unsigned pf[8][4];
        float ps0 = 0.0f, ps1 = 0.0f;
        #pragma unroll
        for (int nt = 0; nt < 16; nt++) {
            float p0 = exp2f(sA[nt][0] - mn0), p1 = exp2f(sA[nt][1] - mn0);
            float p2 = exp2f(sA[nt][2] - mn1), p3 = exp2f(sA[nt][3] - mn1);
            ps0 += p0 + p1; ps1 += p2 + p3;
            __half2 hA = __floats2half2_rn(p0, p1);
            __half2 hB = __floats2half2_rn(p2, p3);
            pf[nt >> 1][(nt & 1) * 2 + 0] = *reinterpret_cast<unsigned*>(&hA);
            pf[nt >> 1][(nt & 1) * 2 + 1] = *reinterpret_cast<unsigned*>(&hB);
        }
        #pragma unroll
        for (int off = 1; off <= 2; off <<= 1) {
            ps0 += __shfl_xor_sync(0xffffffffu, ps0, off);
            ps1 += __shfl_xor_sync(0xffffffffu, ps1, off);
        }
        l_i[0] = l_i[0] * al0 + ps0;
        l_i[1] = l_i[1] * al1 + ps1;
        m_i[0] = mn0; m_i[1] = mn1;
        #pragma unroll
        for (int nt = 0; nt < 8; nt++) {
            oAcc[nt][0] *= al0; oAcc[nt][1] *= al0;
            oAcc[nt][2] *= al1; oAcc[nt][3] *= al1;
        }

        // ---- O += P @ V (k-dim 128 -> 8 kt steps) ----
        #pragma unroll
        for (int kt = 0; kt < 8; kt++) {
            unsigned vf[8][2];
            #pragma unroll
            for (int np = 0; np < 4; np++) {
                int row = kt * 16 + (lane & 15);
                unsigned r4[4];
                ldsm4t(r4, sV + SW(row * 128 + np * 32 + ((lane & 16) ? 16 : 0)));
                vf[2 * np][0] = r4[0]; vf[2 * np][1] = r4[1];
                vf[2 * np + 1][0] = r4[2]; vf[2 * np + 1][1] = r4[3];
            }
            #pragma unroll
            for (int nt = 0; nt < 8; nt++)
                mma16(oAcc[nt], pf[kt], vf[nt]);
        }

        if (kb + 2 < nkb) {
            __syncthreads();               // all warps done reading stage kb&1
            fillKV(kb & 1, kb + 2);
            CP_COMMIT();
        }
    }

    // ---- epilogue: normalize, store y (half) ----
    float inv0 = 1.0f / l_i[0], inv1 = 1.0f / l_i[1];
    int qr = q0 + w16 + g;
    __half* yo = y + ((size_t)b * T_ + qr) * C_ + h * D_;
    #pragma unroll
    for (int nt = 0; nt < 8; nt++) {
        int col = nt * 8 + 2 * t;
        *reinterpret_cast<__half2*>(yo + col) =
            __floats2half2_rn(oAcc[nt][0] * inv0, oAcc[nt][1] * inv0);
        *reinterpret_cast<__half2*>(yo + (size_t)8 * C_ + col) =
            __floats2half2_rn(oAcc[nt][2] * inv1, oAcc[nt][3] * inv1);
    }
}

// ---------------------------------------------------------------------------
extern "C" void kernel_launch(void* const* d_in, const int* in_sizes, int n_in,
                              void* d_out, int out_size) {
    const float* x        = (const float*)d_in[0];
    const float* c_attn_w = (const float*)d_in[1];
    const float* c_attn_b = (const float*)d_in[2];
    const float* c_proj_w = (const float*)d_in[3];
    const float* c_proj_b = (const float*)d_in[4];
    float* out = (float*)d_out;

    __half *xh, *wq, *wp, *qkvh, *yh;
    cudaGetSymbolAddress((void**)&xh,   g_xh);
    cudaGetSymbolAddress((void**)&wq,   g_wqkv);
    cudaGetSymbolAddress((void**)&wp,   g_wproj);
    cudaGetSymbolAddress((void**)&qkvh, g_qkvh);
    cudaGetSymbolAddress((void**)&yh,   g_yh);

    // 0) one-time fp32 -> fp16 conversions (single launch)
    int n0 = (M_ * C_) / 4, n1 = (C_ * 3 * C_) / 4, n2 = (C_ * C_) / 4;
    f2h_all<<<(n0 + n1 + n2 + 255) / 256, 256>>>(x, xh, n0, c_attn_w, wq, n1, c_proj_w, wp, n2);

    size_t gsQ = (size_t)2 * QSTG;               // 53248 B -> occ 4
    size_t gsP = (size_t)3 * PSTG;               // 41472 B -> occ 4
    cudaFuncSetAttribute(gemm_q, cudaFuncAttributeMaxDynamicSharedMemorySize, (int)gsQ);
    cudaFuncSetAttribute(gemm_p, cudaFuncAttributeMaxDynamicSharedMemorySize, (int)gsP);
    size_t as = (size_t)QSZ + 2 * KVSTG2;        // 73728 B -> occ 3
    cudaFuncSetAttribute(attn_h, cudaFuncAttributeMaxDynamicSharedMemorySize, (int)as);

    // 1) QKV projection: tile 64x128, BK=64, occ 4, grid (18,64)
    gemm_q<<<dim3((3 * C_) / 128, M_ / 64), 128, gsQ>>>(xh, wq, c_attn_b, qkvh, C_, 3 * C_);

    // 2) Causal flash attention: 64-row q-tiles, 128-key blocks, grid (32,24)
    attn_h<<<dim3(T_ / 64, B_ * H_), 128, as>>>(qkvh, yh);

    // 3) Output projection: tile 64x128, BK=32, occ 4, grid (6,64)
    gemm_p<<<dim3(C_ / 128, M_ / 64), 128, gsP>>>(yh, wp, c_proj_b, out, C_, C_);
}